// round 5
// baseline (speedup 1.0000x reference)
#include <cuda_runtime.h>
#include <cstdint>

// Embed3D: out[nl, p*40 + 2k + {0,1}] = {sin, cos}(x[nl,1+p] * div_term[k])
// x: (NL,4) fp32, div_term: 20 fp32, out: (NL,120) fp32, NL = 64*8192 = 524288.
//
// Store path rework: compute into SMEM, stream out with cp.async.bulk
// (async proxy, bypasses the L1tex store queue that capped prior rounds
// at ~65% DRAM). 4-deep chunk ring, commit_group/wait_group backpressure.
//
// chunk = 16 rows = 1920 floats = 7680 B. 480 threads -> each thread
// computes exactly one float4 per chunk (slot j = tid%30, row r = tid/30).
// STS.128 is bank-conflict-free (8 lanes/phase * 16B = 32 banks).

#define THREADS 480
#define ROWS_PER_CHUNK 16
#define CHUNK_F4 (ROWS_PER_CHUNK * 30)          // 480 float4 = 7680 B
#define CHUNK_BYTES (CHUNK_F4 * 16)
#define NBUF 4
#define CHUNKS_PER_BLOCK 16                      // 256 rows per block

__global__ __launch_bounds__(THREADS)
void embed3d_kernel(const float* __restrict__ x,
                    const float* __restrict__ div_term,
                    float* __restrict__ out) {
    __shared__ float4 sbuf[NBUF][CHUNK_F4];      // 30720 B

    const int tid = threadIdx.x;
    const int j   = tid % 30;                    // float4 slot within a row
    const int r   = tid / 30;                    // row within chunk (0..15)
    const int p   = j / 10;                      // pos component 0..2
    const int q   = j - p * 10;                  // pair group 0..9

    const float d0 = __ldg(&div_term[2 * q]);
    const float d1 = __ldg(&div_term[2 * q + 1]);

    const int chunk0 = blockIdx.x * CHUNKS_PER_BLOCK;

#pragma unroll 1
    for (int c = 0; c < CHUNKS_PER_BLOCK; c++) {
        const int buf = c & (NBUF - 1);
        const int g   = chunk0 + c;              // global chunk id
        const int nl  = g * ROWS_PER_CHUNK + r;

        // Backpressure: buffer `buf` is free once its bulk store (group c-NBUF)
        // has completed, i.e. at most NBUF-1 groups outstanding.
        if (c >= NBUF && tid == 0) {
            asm volatile("cp.async.bulk.wait_group %0;" :: "n"(NBUF - 1) : "memory");
        }
        __syncthreads();

        const float pos = __ldg(&x[nl * 4 + 1 + p]);
        float4 v;
        __sincosf(pos * d0, &v.x, &v.y);
        __sincosf(pos * d1, &v.z, &v.w);
        sbuf[buf][tid] = v;

        __syncthreads();

        if (tid == 0) {
            asm volatile("fence.proxy.async.shared::cta;" ::: "memory");
            uint32_t saddr = (uint32_t)__cvta_generic_to_shared(&sbuf[buf][0]);
            const float* dst = out + (size_t)g * (CHUNK_F4 * 4);
            asm volatile(
                "cp.async.bulk.global.shared::cta.bulk_group [%0], [%1], %2;"
                :: "l"(dst), "r"(saddr), "n"(CHUNK_BYTES) : "memory");
            asm volatile("cp.async.bulk.commit_group;" ::: "memory");
        }
    }

    // Drain all outstanding bulk stores before exit.
    if (tid == 0) {
        asm volatile("cp.async.bulk.wait_group 0;" ::: "memory");
    }
}

extern "C" void kernel_launch(void* const* d_in, const int* in_sizes, int n_in,
                              void* d_out, int out_size) {
    const float* x        = (const float*)d_in[0];
    const float* div_term = (const float*)d_in[1];
    float* out            = (float*)d_out;

    const int total_nl = in_sizes[0] / 4;        // 524288
    const int total_chunks = total_nl / ROWS_PER_CHUNK;          // 32768
    const int grid = total_chunks / CHUNKS_PER_BLOCK;            // 2048

    embed3d_kernel<<<grid, THREADS>>>(x, div_term, out);
}

// round 6
// speedup vs baseline: 1.4306x; 1.4306x over previous
#include <cuda_runtime.h>

// Embed3D: out[nl, p*40 + 2k + {0,1}] = {sin, cos}(x[nl,1+p] * div_term[k])
// x: (NL,4) fp32, div_term: 20 fp32, out: (NL,120) fp32, NL = 64*8192.
//
// R3 direct-store design + Blackwell 256-bit stores.
// Row = 120 floats = 15 float8 slots. blockDim=480 -> 32 rows per slice,
// 4 slices -> 128 rows/block, grid 4096. Global float8 index
// = nl*15 + j8 = blockIdx.x*1920 + s*480 + tid  => contiguous STG.256.
// Each float8 covers 4 (sin,cos) pairs k0..k0+3 within one pos component.

#define THREADS 480
#define ROWS_PER_SLICE 32
#define SLICES 4
#define ROWS_PER_BLOCK (ROWS_PER_SLICE * SLICES)   // 128

__device__ __forceinline__ void stg_cs_v8(float* ptr,
                                          float f0, float f1, float f2, float f3,
                                          float f4, float f5, float f6, float f7) {
    asm volatile(
        "st.global.cs.v8.f32 [%0], {%1, %2, %3, %4, %5, %6, %7, %8};"
        :: "l"(ptr), "f"(f0), "f"(f1), "f"(f2), "f"(f3),
           "f"(f4), "f"(f5), "f"(f6), "f"(f7)
        : "memory");
}

__global__ __launch_bounds__(THREADS)
void embed3d_kernel(const float* __restrict__ x,
                    const float* __restrict__ div_term,
                    float* __restrict__ out,
                    int total_nl) {
    const int tid = threadIdx.x;
    const int j8  = tid % 15;          // float8 slot within a row (0..14)
    const int r   = tid / 15;          // row within slice (0..31)

    const int p  = j8 / 5;             // pos component 0..2
    const int k0 = 4 * (j8 - 5 * p);   // first pair index (0,4,8,12,16)

    const float d0 = __ldg(&div_term[k0]);
    const float d1 = __ldg(&div_term[k0 + 1]);
    const float d2 = __ldg(&div_term[k0 + 2]);
    const float d3 = __ldg(&div_term[k0 + 3]);

    const int nl_base = blockIdx.x * ROWS_PER_BLOCK + r;

    // Front-batch the pos loads: 4 independent LDGs in flight.
    float pos[SLICES];
#pragma unroll
    for (int s = 0; s < SLICES; s++) {
        const int nl = nl_base + s * ROWS_PER_SLICE;
        pos[s] = __ldg(&x[nl * 4 + 1 + p]);
    }

#pragma unroll
    for (int s = 0; s < SLICES; s++) {
        const int nl = nl_base + s * ROWS_PER_SLICE;
        float s0, c0, s1, c1, s2, c2, s3, c3;
        __sincosf(pos[s] * d0, &s0, &c0);
        __sincosf(pos[s] * d1, &s1, &c1);
        __sincosf(pos[s] * d2, &s2, &c2);
        __sincosf(pos[s] * d3, &s3, &c3);
        stg_cs_v8(out + (size_t)(nl * 15 + j8) * 8,
                  s0, c0, s1, c1, s2, c2, s3, c3);
    }
}

extern "C" void kernel_launch(void* const* d_in, const int* in_sizes, int n_in,
                              void* d_out, int out_size) {
    const float* x        = (const float*)d_in[0];
    const float* div_term = (const float*)d_in[1];
    float* out            = (float*)d_out;

    const int total_nl = in_sizes[0] / 4;   // 524288, divisible by 128
    const int grid = total_nl / ROWS_PER_BLOCK;

    embed3d_kernel<<<grid, THREADS>>>(x, div_term, out, total_nl);
}